// round 11
// baseline (speedup 1.0000x reference)
// R11: retry of the R10 kernel — broker failed twice (same infra signature as
// R2/R3/R6/R8; unchanged resubmits passed every time). Audit clean; unchanged.
#include <cuda_runtime.h>
#include <math.h>
#include <stdint.h>

#define NMAX 50048
#define EMAX 500224

// ---------------- static scratch ----------------
__device__ __align__(256) int   g_degi[NMAX];
__device__ __align__(256) int   g_rowoff[NMAX + 8];
__device__ __align__(256) int   g_cursor[NMAX];
__device__ __align__(256) int   g_csr_src[EMAX];
__device__ __align__(256) int   g_csr_eid[EMAX];
__device__ __align__(256) float g_inv[NMAX];
__device__ __align__(256) float g_aggh1[NMAX * 64];
__device__ __align__(256) float g_agge1[NMAX * 64];
__device__ __align__(256) float g_agg2[NMAX * 128];   // [0:NMAX*64) h-part, [NMAX*64:) e-part
__device__ __align__(256) float g_h1[NMAX * 64];
__device__ __align__(256) float g_ac1[NMAX * 128];
__device__ __align__(256) float g_ac2[NMAX * 128];
__device__ __align__(256) float g_V1[128 * 64];
__device__ __align__(256) float g_V2[128 * 64];
__device__ __align__(256) float g_small[192];         // 0:64 colsum, 64:128 v, 128/129 loss

__device__ __forceinline__ float reluf(float x) { return fmaxf(x, 0.f); }
__device__ __forceinline__ float softplusf(float x) {
    return fmaxf(x, 0.f) + log1pf(expf(-fabsf(x)));
}
__device__ __forceinline__ uint32_t f2tf(float x) {
    uint32_t u;
    asm("cvt.rna.tf32.f32 %0, %1;" : "=r"(u) : "f"(x));
    return u;
}
__device__ __forceinline__ void mma_tf32(float c[4], uint32_t a0, uint32_t a1, uint32_t a2,
                                         uint32_t a3, uint32_t b0, uint32_t b1) {
    asm volatile(
        "mma.sync.aligned.m16n8k8.row.col.f32.tf32.tf32.f32 "
        "{%0,%1,%2,%3}, {%4,%5,%6,%7}, {%8,%9}, {%0,%1,%2,%3};"
        : "+f"(c[0]), "+f"(c[1]), "+f"(c[2]), "+f"(c[3])
        : "r"(a0), "r"(a1), "r"(a2), "r"(a3), "r"(b0), "r"(b1));
}

__global__ void zero_kernel(float* p, int n) {
    int i = blockIdx.x * blockDim.x + threadIdx.x;
    if (i < n) p[i] = 0.f;
}

__global__ void count_kernel(const int* __restrict__ dst, int E) {
    int i = blockIdx.x * blockDim.x + threadIdx.x;
    if (i < E) atomicAdd(&g_degi[dst[i]], 1);
}

// Single-block scan: row offsets, fill cursors, inv_deg. 1024 threads.
__global__ void scan_kernel(int N, int E) {
    __shared__ int ps[1024];
    const int C = (NMAX + 1023) / 1024;
    int t = threadIdx.x;
    int base = t * C;
    int local = 0;
    for (int i = 0; i < C; i++) {
        int n = base + i;
        if (n < N) local += g_degi[n];
    }
    ps[t] = local;
    __syncthreads();
    for (int o = 1; o < 1024; o <<= 1) {
        int v = (t >= o) ? ps[t - o] : 0;
        __syncthreads();
        ps[t] += v;
        __syncthreads();
    }
    int run = ps[t] - local;
    for (int i = 0; i < C; i++) {
        int n = base + i;
        if (n < N) {
            g_rowoff[n] = run;
            g_cursor[n] = run;
            int d = g_degi[n];
            g_inv[n] = 1.f / fmaxf((float)d, 1.f);
            run += d;
        }
    }
    if (t == 1023) g_rowoff[N] = E;
}

__global__ void fill_kernel(const int* __restrict__ src, const int* __restrict__ dst, int E) {
    int e = blockIdx.x * blockDim.x + threadIdx.x;
    if (e >= E) return;
    int d = dst[e];
    int p = atomicAdd(&g_cursor[d], 1);
    g_csr_src[p] = src[e];
    g_csr_eid[p] = e;
}

// V[128][64]: rows 0..63 = W_edge[:,0:64] (src half), 64..127 = W_edge[:,64:128] (dst half)
__global__ void vprep_kernel(const float* __restrict__ We, float* __restrict__ V) {
    int i = blockIdx.x * blockDim.x + threadIdx.x;
    if (i >= 128 * 64) return;
    int j = i >> 6, k = i & 63;
    V[i] = (j < 64) ? We[j * 128 + k] : We[(j - 64) * 128 + 64 + k];
}

// POS layer-1 gather, 32 thr/node: lanes 0-15 mean nf[src] -> aggh1; 16-31 mean ef[eid] -> agge1.
__global__ void gather1_pos_kernel(const float* __restrict__ nf, const float* __restrict__ ef, int N) {
    int idx = blockIdx.x * blockDim.x + threadIdx.x;
    int n = idx >> 5, lane = idx & 31;
    if (n >= N) return;
    int b = g_rowoff[n], e = g_rowoff[n + 1];
    float iv = g_inv[n];
    float4 acc = make_float4(0.f, 0.f, 0.f, 0.f);
    if (lane < 16) {
        int c4 = lane * 4;
        for (int i = b; i < e; i++) {
            int s = g_csr_src[i];
            float4 v = *(const float4*)(nf + (long long)s * 64 + c4);
            acc.x += v.x; acc.y += v.y; acc.z += v.z; acc.w += v.w;
        }
        acc.x *= iv; acc.y *= iv; acc.z *= iv; acc.w *= iv;
        *(float4*)(g_aggh1 + (long long)n * 64 + c4) = acc;
    } else {
        int c4 = (lane - 16) * 4;
        for (int i = b; i < e; i++) {
            int eid = g_csr_eid[i];
            float4 v = *(const float4*)(ef + (long long)eid * 64 + c4);
            acc.x += v.x; acc.y += v.y; acc.z += v.z; acc.w += v.w;
        }
        acc.x *= iv; acc.y *= iv; acc.z *= iv; acc.w *= iv;
        *(float4*)(g_agge1 + (long long)n * 64 + c4) = acc;
    }
}

// NEG layer-1 edge-feat gather: agge1[n] = mean ef[perm[eid]]. 16 thr/node.
__global__ void gather_ef_neg_kernel(const float* __restrict__ ef, const int* __restrict__ perm, int N) {
    int idx = blockIdx.x * blockDim.x + threadIdx.x;
    int n = idx >> 4, l = idx & 15;
    if (n >= N) return;
    int b = g_rowoff[n], e = g_rowoff[n + 1];
    float4 acc = make_float4(0.f, 0.f, 0.f, 0.f);
    for (int i = b; i < e; i++) {
        int eid = perm[g_csr_eid[i]];
        float4 v = *(const float4*)(ef + (long long)eid * 64 + l * 4);
        acc.x += v.x; acc.y += v.y; acc.z += v.z; acc.w += v.w;
    }
    float iv = g_inv[n];
    acc.x *= iv; acc.y *= iv; acc.z *= iv; acc.w *= iv;
    *(float4*)(g_agge1 + (long long)n * 64 + l * 4) = acc;
}

// layer-2 gather: h-part = mean h1[src]; e-part = mean relu(a1[src]+c1[n]+be1). 32 thr/node.
__global__ void gather2_kernel(const float* __restrict__ bE1, int N) {
    int idx = blockIdx.x * blockDim.x + threadIdx.x;
    int n = idx >> 5, lane = idx & 31;
    if (n >= N) return;
    int b = g_rowoff[n], e = g_rowoff[n + 1];
    float iv = g_inv[n];
    if (lane < 16) {
        int c4 = lane * 4;
        float4 acc = make_float4(0.f, 0.f, 0.f, 0.f);
        for (int i = b; i < e; i++) {
            int s = g_csr_src[i];
            float4 v = *(const float4*)(g_h1 + (long long)s * 64 + c4);
            acc.x += v.x; acc.y += v.y; acc.z += v.z; acc.w += v.w;
        }
        acc.x *= iv; acc.y *= iv; acc.z *= iv; acc.w *= iv;
        *(float4*)(g_agg2 + (long long)n * 64 + c4) = acc;
    } else {
        int c4 = (lane - 16) * 4;
        float4 cv = *(const float4*)(g_ac1 + (long long)n * 128 + 64 + c4);
        float4 bv = *(const float4*)(bE1 + c4);
        cv.x += bv.x; cv.y += bv.y; cv.z += bv.z; cv.w += bv.w;
        float4 acc = make_float4(0.f, 0.f, 0.f, 0.f);
        for (int i = b; i < e; i++) {
            int s = g_csr_src[i];
            float4 a = *(const float4*)(g_ac1 + (long long)s * 128 + c4);
            acc.x += reluf(a.x + cv.x);
            acc.y += reluf(a.y + cv.y);
            acc.z += reluf(a.z + cv.z);
            acc.w += reluf(a.w + cv.w);
        }
        acc.x *= iv; acc.y *= iv; acc.z *= iv; acc.w *= iv;
        *(float4*)(g_agg2 + (long long)NMAX * 64 + (long long)n * 64 + c4) = acc;
    }
}

// ---------------- fused tf32-mma layer kernel (unchanged) ----------------
#define HS_OFF 0
#define XS_OFF 8704
#define WS_OFF (8704 + 4608)
#define VS_OFF 8704
#define SM_FLOATS (8704 + 8704)
#define SM_BYTES (SM_FLOATS * 4)

template <bool WRITE_H>
__global__ __launch_bounds__(256, 2)
void layer_kernel(const float* __restrict__ hin, const float* __restrict__ aggh,
                  const float* __restrict__ agge, const float* __restrict__ Wa,
                  const float* __restrict__ ba, const float* __restrict__ V,
                  float* __restrict__ hout, float* __restrict__ ac, int M) {
    extern __shared__ float sm[];
    float*    Hs = sm + HS_OFF;
    uint32_t* Xs = (uint32_t*)(sm + XS_OFF);
    uint32_t* Ws = (uint32_t*)(sm + WS_OFF);
    uint32_t* Vs = (uint32_t*)(sm + VS_OFF);

    int tid = threadIdx.x;
    int wid = tid >> 5, lane = tid & 31;
    int gid = lane >> 2, tig = lane & 3;
    int m0 = blockIdx.x * 128;
    int mbase = wid * 16;

    float c1[8][4];
#pragma unroll
    for (int i = 0; i < 8; i++)
#pragma unroll
        for (int j = 0; j < 4; j++) c1[i][j] = 0.f;

    for (int c0 = 0; c0 < 192; c0 += 32) {
        const float* srcp = (c0 < 64) ? (hin + c0) : (c0 < 128) ? (aggh + (c0 - 64)) : (agge + (c0 - 128));
#pragma unroll
        for (int i = 0; i < 4; i++) {
            int q = tid + i * 256;
            int m = q >> 3, c4 = (q & 7) * 4;
            int mg = m0 + m;
            float4 v = make_float4(0.f, 0.f, 0.f, 0.f);
            if (mg < M) v = *(const float4*)(srcp + (long long)mg * 64 + c4);
            uint32_t* p = Xs + m * 36 + c4;
            p[0] = f2tf(v.x); p[1] = f2tf(v.y); p[2] = f2tf(v.z); p[3] = f2tf(v.w);
        }
#pragma unroll
        for (int i = 0; i < 2; i++) {
            int q = tid + i * 256;
            int n = q >> 3, c4 = (q & 7) * 4;
            float4 w = *(const float4*)(Wa + n * 192 + c0 + c4);
            uint32_t* p = Ws + n * 36 + c4;
            p[0] = f2tf(w.x); p[1] = f2tf(w.y); p[2] = f2tf(w.z); p[3] = f2tf(w.w);
        }
        __syncthreads();
#pragma unroll
        for (int kk = 0; kk < 32; kk += 8) {
            uint32_t a0 = Xs[(mbase + gid) * 36 + kk + tig];
            uint32_t a1 = Xs[(mbase + gid + 8) * 36 + kk + tig];
            uint32_t a2 = Xs[(mbase + gid) * 36 + kk + tig + 4];
            uint32_t a3 = Xs[(mbase + gid + 8) * 36 + kk + tig + 4];
#pragma unroll
            for (int nt = 0; nt < 8; nt++) {
                uint32_t b0 = Ws[(nt * 8 + gid) * 36 + kk + tig];
                uint32_t b1 = Ws[(nt * 8 + gid) * 36 + kk + tig + 4];
                mma_tf32(c1[nt], a0, a1, a2, a3, b0, b1);
            }
        }
        __syncthreads();
    }

#pragma unroll
    for (int nt = 0; nt < 8; nt++) {
        int n = nt * 8 + tig * 2;
        float bv0 = ba[n], bv1 = ba[n + 1];
        int r0 = mbase + gid, r1 = r0 + 8;
        Hs[r0 * 68 + n]     = reluf(c1[nt][0] + bv0);
        Hs[r0 * 68 + n + 1] = reluf(c1[nt][1] + bv1);
        Hs[r1 * 68 + n]     = reluf(c1[nt][2] + bv0);
        Hs[r1 * 68 + n + 1] = reluf(c1[nt][3] + bv1);
    }
#pragma unroll
    for (int i = 0; i < 8; i++) {
        int q = tid + i * 256;
        int n = q >> 4, k4 = (q & 15) * 4;
        float4 w = *(const float4*)(V + n * 64 + k4);
        uint32_t* p = Vs + n * 68 + k4;
        p[0] = f2tf(w.x); p[1] = f2tf(w.y); p[2] = f2tf(w.z); p[3] = f2tf(w.w);
    }
    __syncthreads();

    if (WRITE_H) {
#pragma unroll
        for (int i = 0; i < 8; i++) {
            int q = tid + i * 256;
            int m = q >> 4, c4 = (q & 15) * 4;
            int mg = m0 + m;
            if (mg < M) *(float4*)(hout + (long long)mg * 64 + c4) = *(const float4*)(Hs + m * 68 + c4);
        }
    }

    float c2[16][4];
#pragma unroll
    for (int i = 0; i < 16; i++)
#pragma unroll
        for (int j = 0; j < 4; j++) c2[i][j] = 0.f;

#pragma unroll
    for (int k0 = 0; k0 < 64; k0 += 8) {
        uint32_t a0 = f2tf(Hs[(mbase + gid) * 68 + k0 + tig]);
        uint32_t a1 = f2tf(Hs[(mbase + gid + 8) * 68 + k0 + tig]);
        uint32_t a2 = f2tf(Hs[(mbase + gid) * 68 + k0 + tig + 4]);
        uint32_t a3 = f2tf(Hs[(mbase + gid + 8) * 68 + k0 + tig + 4]);
#pragma unroll
        for (int nt = 0; nt < 16; nt++) {
            uint32_t b0 = Vs[(nt * 8 + gid) * 68 + k0 + tig];
            uint32_t b1 = Vs[(nt * 8 + gid) * 68 + k0 + tig + 4];
            mma_tf32(c2[nt], a0, a1, a2, a3, b0, b1);
        }
    }

    int r0g = m0 + mbase + gid, r1g = r0g + 8;
#pragma unroll
    for (int nt = 0; nt < 16; nt++) {
        int n = nt * 8 + tig * 2;
        if (r0g < M) *(float2*)(ac + (long long)r0g * 128 + n) = make_float2(c2[nt][0], c2[nt][1]);
        if (r1g < M) *(float2*)(ac + (long long)r1g * 128 + n) = make_float2(c2[nt][2], c2[nt][3]);
    }
}

// CSR colsum: warp per node; lane holds cols (lane, lane+32) of dst-half + bias.
// Per edge reads only ac2[s][0:64] (256B coalesced). Per-lane accumulators.
__global__ void colsum_csr_kernel(const float* __restrict__ bE2, int N) {
    __shared__ float sh[64];
    int tid = threadIdx.x;
    if (tid < 64) sh[tid] = 0.f;
    __syncthreads();
    int lane = tid & 31;
    int w = (blockIdx.x * blockDim.x + tid) >> 5;
    int nwarp = (gridDim.x * blockDim.x) >> 5;
    float b0 = bE2[lane], b1 = bE2[lane + 32];
    float cs0 = 0.f, cs1 = 0.f;
    for (int n = w; n < N; n += nwarp) {
        int b = g_rowoff[n], e = g_rowoff[n + 1];
        if (b == e) continue;
        float c0 = g_ac2[(long long)n * 128 + 64 + lane] + b0;
        float c1 = g_ac2[(long long)n * 128 + 96 + lane] + b1;
        for (int i = b; i < e; i++) {
            int s = g_csr_src[i];
            cs0 += reluf(g_ac2[(long long)s * 128 + lane] + c0);
            cs1 += reluf(g_ac2[(long long)s * 128 + 32 + lane] + c1);
        }
    }
    atomicAdd(&sh[lane], cs0);
    atomicAdd(&sh[lane + 32], cs1);
    __syncthreads();
    if (tid < 64) atomicAdd(&g_small[tid], sh[tid]);
}

__global__ void summary_kernel(const float* __restrict__ Wbil, int E) {
    __shared__ float s[64];
    int t = threadIdx.x;  // 64
    s[t] = 1.f / (1.f + expf(-g_small[t] / (float)E));
    __syncthreads();
    float acc = 0.f;
    for (int f = 0; f < 64; f++) acc += Wbil[t * 64 + f] * s[f];
    g_small[64 + t] = acc;
}

// CSR score: warp per node; per edge one shfl-reduce + softplus on lane 0.
template <bool NEGATE>
__global__ void score_csr_kernel(const float* __restrict__ bE2, const float* __restrict__ bbil,
                                 int N, int slot) {
    int tid = threadIdx.x;
    int lane = tid & 31;
    int wi = tid >> 5;
    int w = (blockIdx.x * blockDim.x + tid) >> 5;
    int nwarp = (gridDim.x * blockDim.x) >> 5;
    float v0 = g_small[64 + lane], v1 = g_small[96 + lane];
    float b0 = bE2[lane], b1 = bE2[lane + 32];
    float bb = bbil[0];
    float lsum = 0.f;
    for (int n = w; n < N; n += nwarp) {
        int b = g_rowoff[n], e = g_rowoff[n + 1];
        if (b == e) continue;
        float c0 = g_ac2[(long long)n * 128 + 64 + lane] + b0;
        float c1 = g_ac2[(long long)n * 128 + 96 + lane] + b1;
        for (int i = b; i < e; i++) {
            int s = g_csr_src[i];
            float t0 = reluf(g_ac2[(long long)s * 128 + lane] + c0) * v0;
            float t1 = reluf(g_ac2[(long long)s * 128 + 32 + lane] + c1) * v1;
            float p = t0 + t1;
#pragma unroll
            for (int o = 16; o > 0; o >>= 1) p += __shfl_xor_sync(0xffffffffu, p, o);
            if (lane == 0) {
                float x = p + bb;
                if (NEGATE) x = -x;
                lsum += softplusf(x);
            }
        }
    }
    __shared__ float sh[8];
    if (lane == 0) sh[wi] = lsum;
    __syncthreads();
    if (tid == 0) {
        float t = 0.f;
        int nw = blockDim.x >> 5;
        for (int i = 0; i < nw; i++) t += sh[i];
        atomicAdd(&g_small[128 + slot], t);
    }
}

__global__ void final_kernel(float* out, int E) {
    out[0] = g_small[128] / (float)E + g_small[129] / (float)E;
}

// ---------------- host launch ----------------
extern "C" void kernel_launch(void* const* d_in, const int* in_sizes, int n_in,
                              void* d_out, int out_size) {
    const float* nf   = (const float*)d_in[0];
    const float* ef   = (const float*)d_in[1];
    const int*   src  = (const int*)d_in[2];
    const int*   dst  = (const int*)d_in[3];
    const int*   perm = (const int*)d_in[4];
    const float* Wa1  = (const float*)d_in[5];
    const float* ba1  = (const float*)d_in[6];
    const float* We1  = (const float*)d_in[7];
    const float* be1  = (const float*)d_in[8];
    const float* Wa2  = (const float*)d_in[9];
    const float* ba2  = (const float*)d_in[10];
    const float* We2  = (const float*)d_in[11];
    const float* be2  = (const float*)d_in[12];
    const float* Wbil = (const float*)d_in[13];
    const float* bbil = (const float*)d_in[14];

    int N = in_sizes[0] / 64;
    int E = in_sizes[2];
    if (N > NMAX) N = NMAX;
    if (E > EMAX) E = EMAX;

    static int attr_done = 0;
    if (!attr_done) {
        cudaFuncSetAttribute(layer_kernel<true>,  cudaFuncAttributeMaxDynamicSharedMemorySize, SM_BYTES);
        cudaFuncSetAttribute(layer_kernel<false>, cudaFuncAttributeMaxDynamicSharedMemorySize, SM_BYTES);
        attr_done = 1;
    }

    float *p_aggh1, *p_agge1, *p_agg2, *p_h1, *p_ac1, *p_ac2, *p_V1, *p_V2, *p_small;
    int* p_degi;
    cudaGetSymbolAddress((void**)&p_degi, g_degi);
    cudaGetSymbolAddress((void**)&p_aggh1, g_aggh1);
    cudaGetSymbolAddress((void**)&p_agge1, g_agge1);
    cudaGetSymbolAddress((void**)&p_agg2, g_agg2);
    cudaGetSymbolAddress((void**)&p_h1, g_h1);
    cudaGetSymbolAddress((void**)&p_ac1, g_ac1);
    cudaGetSymbolAddress((void**)&p_ac2, g_ac2);
    cudaGetSymbolAddress((void**)&p_V1, g_V1);
    cudaGetSymbolAddress((void**)&p_V2, g_V2);
    cudaGetSymbolAddress((void**)&p_small, g_small);

    const int B = 256;
    auto g = [](long long n) { return (unsigned)((n + 255) / 256); };
    int layer_grid = (N + 127) / 128;
    unsigned g16 = g((long long)N * 16), g32 = g((long long)N * 32);

    // Setup
    zero_kernel<<<g(N), B>>>((float*)p_degi, N);
    count_kernel<<<g(E), B>>>(dst, E);
    scan_kernel<<<1, 1024>>>(N, E);
    fill_kernel<<<g(E), B>>>(src, dst, E);
    gather1_pos_kernel<<<g32, B>>>(nf, ef, N);
    vprep_kernel<<<g(128 * 64), B>>>(We1, p_V1);
    vprep_kernel<<<g(128 * 64), B>>>(We2, p_V2);
    zero_kernel<<<1, 192>>>(p_small, 192);

    // ======== POS ========
    layer_kernel<true><<<layer_grid, 256, SM_BYTES>>>(nf, p_aggh1, p_agge1, Wa1, ba1, p_V1, p_h1, p_ac1, N);
    gather2_kernel<<<g32, B>>>(be1, N);
    layer_kernel<false><<<layer_grid, 256, SM_BYTES>>>(p_h1, p_agg2, p_agg2 + (long long)NMAX * 64, Wa2, ba2, p_V2, nullptr, p_ac2, N);
    colsum_csr_kernel<<<192, 256>>>(be2, N);
    summary_kernel<<<1, 64>>>(Wbil, E);
    score_csr_kernel<true><<<256, 256>>>(be2, bbil, N, 0);

    // ======== NEG ========
    gather_ef_neg_kernel<<<g16, B>>>(ef, perm, N);
    layer_kernel<true><<<layer_grid, 256, SM_BYTES>>>(nf, p_aggh1, p_agge1, Wa1, ba1, p_V1, p_h1, p_ac1, N);
    gather2_kernel<<<g32, B>>>(be1, N);
    layer_kernel<false><<<layer_grid, 256, SM_BYTES>>>(p_h1, p_agg2, p_agg2 + (long long)NMAX * 64, Wa2, ba2, p_V2, nullptr, p_ac2, N);
    score_csr_kernel<false><<<256, 256>>>(be2, bbil, N, 1);

    final_kernel<<<1, 1>>>((float*)d_out, E);
}

// round 13
// speedup vs baseline: 1.3509x; 1.3509x over previous
// R12: R11 kernels unchanged; ONLY the colsum/score grid sizes fixed
// (256/192 blocks starved the warp-per-node kernels -> R11 regression).
#include <cuda_runtime.h>
#include <math.h>
#include <stdint.h>

#define NMAX 50048
#define EMAX 500224

// ---------------- static scratch ----------------
__device__ __align__(256) int   g_degi[NMAX];
__device__ __align__(256) int   g_rowoff[NMAX + 8];
__device__ __align__(256) int   g_cursor[NMAX];
__device__ __align__(256) int   g_csr_src[EMAX];
__device__ __align__(256) int   g_csr_eid[EMAX];
__device__ __align__(256) float g_inv[NMAX];
__device__ __align__(256) float g_aggh1[NMAX * 64];
__device__ __align__(256) float g_agge1[NMAX * 64];
__device__ __align__(256) float g_agg2[NMAX * 128];   // [0:NMAX*64) h-part, [NMAX*64:) e-part
__device__ __align__(256) float g_h1[NMAX * 64];
__device__ __align__(256) float g_ac1[NMAX * 128];
__device__ __align__(256) float g_ac2[NMAX * 128];
__device__ __align__(256) float g_V1[128 * 64];
__device__ __align__(256) float g_V2[128 * 64];
__device__ __align__(256) float g_small[192];         // 0:64 colsum, 64:128 v, 128/129 loss

__device__ __forceinline__ float reluf(float x) { return fmaxf(x, 0.f); }
__device__ __forceinline__ float softplusf(float x) {
    return fmaxf(x, 0.f) + log1pf(expf(-fabsf(x)));
}
__device__ __forceinline__ uint32_t f2tf(float x) {
    uint32_t u;
    asm("cvt.rna.tf32.f32 %0, %1;" : "=r"(u) : "f"(x));
    return u;
}
__device__ __forceinline__ void mma_tf32(float c[4], uint32_t a0, uint32_t a1, uint32_t a2,
                                         uint32_t a3, uint32_t b0, uint32_t b1) {
    asm volatile(
        "mma.sync.aligned.m16n8k8.row.col.f32.tf32.tf32.f32 "
        "{%0,%1,%2,%3}, {%4,%5,%6,%7}, {%8,%9}, {%0,%1,%2,%3};"
        : "+f"(c[0]), "+f"(c[1]), "+f"(c[2]), "+f"(c[3])
        : "r"(a0), "r"(a1), "r"(a2), "r"(a3), "r"(b0), "r"(b1));
}

__global__ void zero_kernel(float* p, int n) {
    int i = blockIdx.x * blockDim.x + threadIdx.x;
    if (i < n) p[i] = 0.f;
}

__global__ void count_kernel(const int* __restrict__ dst, int E) {
    int i = blockIdx.x * blockDim.x + threadIdx.x;
    if (i < E) atomicAdd(&g_degi[dst[i]], 1);
}

// Single-block scan: row offsets, fill cursors, inv_deg. 1024 threads.
__global__ void scan_kernel(int N, int E) {
    __shared__ int ps[1024];
    const int C = (NMAX + 1023) / 1024;
    int t = threadIdx.x;
    int base = t * C;
    int local = 0;
    for (int i = 0; i < C; i++) {
        int n = base + i;
        if (n < N) local += g_degi[n];
    }
    ps[t] = local;
    __syncthreads();
    for (int o = 1; o < 1024; o <<= 1) {
        int v = (t >= o) ? ps[t - o] : 0;
        __syncthreads();
        ps[t] += v;
        __syncthreads();
    }
    int run = ps[t] - local;
    for (int i = 0; i < C; i++) {
        int n = base + i;
        if (n < N) {
            g_rowoff[n] = run;
            g_cursor[n] = run;
            int d = g_degi[n];
            g_inv[n] = 1.f / fmaxf((float)d, 1.f);
            run += d;
        }
    }
    if (t == 1023) g_rowoff[N] = E;
}

__global__ void fill_kernel(const int* __restrict__ src, const int* __restrict__ dst, int E) {
    int e = blockIdx.x * blockDim.x + threadIdx.x;
    if (e >= E) return;
    int d = dst[e];
    int p = atomicAdd(&g_cursor[d], 1);
    g_csr_src[p] = src[e];
    g_csr_eid[p] = e;
}

// V[128][64]: rows 0..63 = W_edge[:,0:64] (src half), 64..127 = W_edge[:,64:128] (dst half)
__global__ void vprep_kernel(const float* __restrict__ We, float* __restrict__ V) {
    int i = blockIdx.x * blockDim.x + threadIdx.x;
    if (i >= 128 * 64) return;
    int j = i >> 6, k = i & 63;
    V[i] = (j < 64) ? We[j * 128 + k] : We[(j - 64) * 128 + 64 + k];
}

// POS layer-1 gather, 32 thr/node: lanes 0-15 mean nf[src] -> aggh1; 16-31 mean ef[eid] -> agge1.
__global__ void gather1_pos_kernel(const float* __restrict__ nf, const float* __restrict__ ef, int N) {
    int idx = blockIdx.x * blockDim.x + threadIdx.x;
    int n = idx >> 5, lane = idx & 31;
    if (n >= N) return;
    int b = g_rowoff[n], e = g_rowoff[n + 1];
    float iv = g_inv[n];
    float4 acc = make_float4(0.f, 0.f, 0.f, 0.f);
    if (lane < 16) {
        int c4 = lane * 4;
        for (int i = b; i < e; i++) {
            int s = g_csr_src[i];
            float4 v = *(const float4*)(nf + (long long)s * 64 + c4);
            acc.x += v.x; acc.y += v.y; acc.z += v.z; acc.w += v.w;
        }
        acc.x *= iv; acc.y *= iv; acc.z *= iv; acc.w *= iv;
        *(float4*)(g_aggh1 + (long long)n * 64 + c4) = acc;
    } else {
        int c4 = (lane - 16) * 4;
        for (int i = b; i < e; i++) {
            int eid = g_csr_eid[i];
            float4 v = *(const float4*)(ef + (long long)eid * 64 + c4);
            acc.x += v.x; acc.y += v.y; acc.z += v.z; acc.w += v.w;
        }
        acc.x *= iv; acc.y *= iv; acc.z *= iv; acc.w *= iv;
        *(float4*)(g_agge1 + (long long)n * 64 + c4) = acc;
    }
}

// NEG layer-1 edge-feat gather: agge1[n] = mean ef[perm[eid]]. 16 thr/node.
__global__ void gather_ef_neg_kernel(const float* __restrict__ ef, const int* __restrict__ perm, int N) {
    int idx = blockIdx.x * blockDim.x + threadIdx.x;
    int n = idx >> 4, l = idx & 15;
    if (n >= N) return;
    int b = g_rowoff[n], e = g_rowoff[n + 1];
    float4 acc = make_float4(0.f, 0.f, 0.f, 0.f);
    for (int i = b; i < e; i++) {
        int eid = perm[g_csr_eid[i]];
        float4 v = *(const float4*)(ef + (long long)eid * 64 + l * 4);
        acc.x += v.x; acc.y += v.y; acc.z += v.z; acc.w += v.w;
    }
    float iv = g_inv[n];
    acc.x *= iv; acc.y *= iv; acc.z *= iv; acc.w *= iv;
    *(float4*)(g_agge1 + (long long)n * 64 + l * 4) = acc;
}

// layer-2 gather: h-part = mean h1[src]; e-part = mean relu(a1[src]+c1[n]+be1). 32 thr/node.
__global__ void gather2_kernel(const float* __restrict__ bE1, int N) {
    int idx = blockIdx.x * blockDim.x + threadIdx.x;
    int n = idx >> 5, lane = idx & 31;
    if (n >= N) return;
    int b = g_rowoff[n], e = g_rowoff[n + 1];
    float iv = g_inv[n];
    if (lane < 16) {
        int c4 = lane * 4;
        float4 acc = make_float4(0.f, 0.f, 0.f, 0.f);
        for (int i = b; i < e; i++) {
            int s = g_csr_src[i];
            float4 v = *(const float4*)(g_h1 + (long long)s * 64 + c4);
            acc.x += v.x; acc.y += v.y; acc.z += v.z; acc.w += v.w;
        }
        acc.x *= iv; acc.y *= iv; acc.z *= iv; acc.w *= iv;
        *(float4*)(g_agg2 + (long long)n * 64 + c4) = acc;
    } else {
        int c4 = (lane - 16) * 4;
        float4 cv = *(const float4*)(g_ac1 + (long long)n * 128 + 64 + c4);
        float4 bv = *(const float4*)(bE1 + c4);
        cv.x += bv.x; cv.y += bv.y; cv.z += bv.z; cv.w += bv.w;
        float4 acc = make_float4(0.f, 0.f, 0.f, 0.f);
        for (int i = b; i < e; i++) {
            int s = g_csr_src[i];
            float4 a = *(const float4*)(g_ac1 + (long long)s * 128 + c4);
            acc.x += reluf(a.x + cv.x);
            acc.y += reluf(a.y + cv.y);
            acc.z += reluf(a.z + cv.z);
            acc.w += reluf(a.w + cv.w);
        }
        acc.x *= iv; acc.y *= iv; acc.z *= iv; acc.w *= iv;
        *(float4*)(g_agg2 + (long long)NMAX * 64 + (long long)n * 64 + c4) = acc;
    }
}

// ---------------- fused tf32-mma layer kernel (unchanged) ----------------
#define HS_OFF 0
#define XS_OFF 8704
#define WS_OFF (8704 + 4608)
#define VS_OFF 8704
#define SM_FLOATS (8704 + 8704)
#define SM_BYTES (SM_FLOATS * 4)

template <bool WRITE_H>
__global__ __launch_bounds__(256, 2)
void layer_kernel(const float* __restrict__ hin, const float* __restrict__ aggh,
                  const float* __restrict__ agge, const float* __restrict__ Wa,
                  const float* __restrict__ ba, const float* __restrict__ V,
                  float* __restrict__ hout, float* __restrict__ ac, int M) {
    extern __shared__ float sm[];
    float*    Hs = sm + HS_OFF;
    uint32_t* Xs = (uint32_t*)(sm + XS_OFF);
    uint32_t* Ws = (uint32_t*)(sm + WS_OFF);
    uint32_t* Vs = (uint32_t*)(sm + VS_OFF);

    int tid = threadIdx.x;
    int wid = tid >> 5, lane = tid & 31;
    int gid = lane >> 2, tig = lane & 3;
    int m0 = blockIdx.x * 128;
    int mbase = wid * 16;

    float c1[8][4];
#pragma unroll
    for (int i = 0; i < 8; i++)
#pragma unroll
        for (int j = 0; j < 4; j++) c1[i][j] = 0.f;

    for (int c0 = 0; c0 < 192; c0 += 32) {
        const float* srcp = (c0 < 64) ? (hin + c0) : (c0 < 128) ? (aggh + (c0 - 64)) : (agge + (c0 - 128));
#pragma unroll
        for (int i = 0; i < 4; i++) {
            int q = tid + i * 256;
            int m = q >> 3, c4 = (q & 7) * 4;
            int mg = m0 + m;
            float4 v = make_float4(0.f, 0.f, 0.f, 0.f);
            if (mg < M) v = *(const float4*)(srcp + (long long)mg * 64 + c4);
            uint32_t* p = Xs + m * 36 + c4;
            p[0] = f2tf(v.x); p[1] = f2tf(v.y); p[2] = f2tf(v.z); p[3] = f2tf(v.w);
        }
#pragma unroll
        for (int i = 0; i < 2; i++) {
            int q = tid + i * 256;
            int n = q >> 3, c4 = (q & 7) * 4;
            float4 w = *(const float4*)(Wa + n * 192 + c0 + c4);
            uint32_t* p = Ws + n * 36 + c4;
            p[0] = f2tf(w.x); p[1] = f2tf(w.y); p[2] = f2tf(w.z); p[3] = f2tf(w.w);
        }
        __syncthreads();
#pragma unroll
        for (int kk = 0; kk < 32; kk += 8) {
            uint32_t a0 = Xs[(mbase + gid) * 36 + kk + tig];
            uint32_t a1 = Xs[(mbase + gid + 8) * 36 + kk + tig];
            uint32_t a2 = Xs[(mbase + gid) * 36 + kk + tig + 4];
            uint32_t a3 = Xs[(mbase + gid + 8) * 36 + kk + tig + 4];
#pragma unroll
            for (int nt = 0; nt < 8; nt++) {
                uint32_t b0 = Ws[(nt * 8 + gid) * 36 + kk + tig];
                uint32_t b1 = Ws[(nt * 8 + gid) * 36 + kk + tig + 4];
                mma_tf32(c1[nt], a0, a1, a2, a3, b0, b1);
            }
        }
        __syncthreads();
    }

#pragma unroll
    for (int nt = 0; nt < 8; nt++) {
        int n = nt * 8 + tig * 2;
        float bv0 = ba[n], bv1 = ba[n + 1];
        int r0 = mbase + gid, r1 = r0 + 8;
        Hs[r0 * 68 + n]     = reluf(c1[nt][0] + bv0);
        Hs[r0 * 68 + n + 1] = reluf(c1[nt][1] + bv1);
        Hs[r1 * 68 + n]     = reluf(c1[nt][2] + bv0);
        Hs[r1 * 68 + n + 1] = reluf(c1[nt][3] + bv1);
    }
#pragma unroll
    for (int i = 0; i < 8; i++) {
        int q = tid + i * 256;
        int n = q >> 4, k4 = (q & 15) * 4;
        float4 w = *(const float4*)(V + n * 64 + k4);
        uint32_t* p = Vs + n * 68 + k4;
        p[0] = f2tf(w.x); p[1] = f2tf(w.y); p[2] = f2tf(w.z); p[3] = f2tf(w.w);
    }
    __syncthreads();

    if (WRITE_H) {
#pragma unroll
        for (int i = 0; i < 8; i++) {
            int q = tid + i * 256;
            int m = q >> 4, c4 = (q & 15) * 4;
            int mg = m0 + m;
            if (mg < M) *(float4*)(hout + (long long)mg * 64 + c4) = *(const float4*)(Hs + m * 68 + c4);
        }
    }

    float c2[16][4];
#pragma unroll
    for (int i = 0; i < 16; i++)
#pragma unroll
        for (int j = 0; j < 4; j++) c2[i][j] = 0.f;

#pragma unroll
    for (int k0 = 0; k0 < 64; k0 += 8) {
        uint32_t a0 = f2tf(Hs[(mbase + gid) * 68 + k0 + tig]);
        uint32_t a1 = f2tf(Hs[(mbase + gid + 8) * 68 + k0 + tig]);
        uint32_t a2 = f2tf(Hs[(mbase + gid) * 68 + k0 + tig + 4]);
        uint32_t a3 = f2tf(Hs[(mbase + gid + 8) * 68 + k0 + tig + 4]);
#pragma unroll
        for (int nt = 0; nt < 16; nt++) {
            uint32_t b0 = Vs[(nt * 8 + gid) * 68 + k0 + tig];
            uint32_t b1 = Vs[(nt * 8 + gid) * 68 + k0 + tig + 4];
            mma_tf32(c2[nt], a0, a1, a2, a3, b0, b1);
        }
    }

    int r0g = m0 + mbase + gid, r1g = r0g + 8;
#pragma unroll
    for (int nt = 0; nt < 16; nt++) {
        int n = nt * 8 + tig * 2;
        if (r0g < M) *(float2*)(ac + (long long)r0g * 128 + n) = make_float2(c2[nt][0], c2[nt][1]);
        if (r1g < M) *(float2*)(ac + (long long)r1g * 128 + n) = make_float2(c2[nt][2], c2[nt][3]);
    }
}

// CSR colsum: warp per node; lane holds cols (lane, lane+32) of dst-half + bias.
__global__ void colsum_csr_kernel(const float* __restrict__ bE2, int N) {
    __shared__ float sh[64];
    int tid = threadIdx.x;
    if (tid < 64) sh[tid] = 0.f;
    __syncthreads();
    int lane = tid & 31;
    int w = (blockIdx.x * blockDim.x + tid) >> 5;
    int nwarp = (gridDim.x * blockDim.x) >> 5;
    float b0 = bE2[lane], b1 = bE2[lane + 32];
    float cs0 = 0.f, cs1 = 0.f;
    for (int n = w; n < N; n += nwarp) {
        int b = g_rowoff[n], e = g_rowoff[n + 1];
        if (b == e) continue;
        float c0 = g_ac2[(long long)n * 128 + 64 + lane] + b0;
        float c1 = g_ac2[(long long)n * 128 + 96 + lane] + b1;
        for (int i = b; i < e; i++) {
            int s = g_csr_src[i];
            cs0 += reluf(g_ac2[(long long)s * 128 + lane] + c0);
            cs1 += reluf(g_ac2[(long long)s * 128 + 32 + lane] + c1);
        }
    }
    atomicAdd(&sh[lane], cs0);
    atomicAdd(&sh[lane + 32], cs1);
    __syncthreads();
    if (tid < 64) atomicAdd(&g_small[tid], sh[tid]);
}

__global__ void summary_kernel(const float* __restrict__ Wbil, int E) {
    __shared__ float s[64];
    int t = threadIdx.x;  // 64
    s[t] = 1.f / (1.f + expf(-g_small[t] / (float)E));
    __syncthreads();
    float acc = 0.f;
    for (int f = 0; f < 64; f++) acc += Wbil[t * 64 + f] * s[f];
    g_small[64 + t] = acc;
}

// CSR score: warp per node; per edge one shfl-reduce + softplus on lane 0.
template <bool NEGATE>
__global__ void score_csr_kernel(const float* __restrict__ bE2, const float* __restrict__ bbil,
                                 int N, int slot) {
    int tid = threadIdx.x;
    int lane = tid & 31;
    int wi = tid >> 5;
    int w = (blockIdx.x * blockDim.x + tid) >> 5;
    int nwarp = (gridDim.x * blockDim.x) >> 5;
    float v0 = g_small[64 + lane], v1 = g_small[96 + lane];
    float b0 = bE2[lane], b1 = bE2[lane + 32];
    float bb = bbil[0];
    float lsum = 0.f;
    for (int n = w; n < N; n += nwarp) {
        int b = g_rowoff[n], e = g_rowoff[n + 1];
        if (b == e) continue;
        float c0 = g_ac2[(long long)n * 128 + 64 + lane] + b0;
        float c1 = g_ac2[(long long)n * 128 + 96 + lane] + b1;
        for (int i = b; i < e; i++) {
            int s = g_csr_src[i];
            float t0 = reluf(g_ac2[(long long)s * 128 + lane] + c0) * v0;
            float t1 = reluf(g_ac2[(long long)s * 128 + 32 + lane] + c1) * v1;
            float p = t0 + t1;
#pragma unroll
            for (int o = 16; o > 0; o >>= 1) p += __shfl_xor_sync(0xffffffffu, p, o);
            if (lane == 0) {
                float x = p + bb;
                if (NEGATE) x = -x;
                lsum += softplusf(x);
            }
        }
    }
    __shared__ float sh[8];
    if (lane == 0) sh[wi] = lsum;
    __syncthreads();
    if (tid == 0) {
        float t = 0.f;
        int nw = blockDim.x >> 5;
        for (int i = 0; i < nw; i++) t += sh[i];
        atomicAdd(&g_small[128 + slot], t);
    }
}

__global__ void final_kernel(float* out, int E) {
    out[0] = g_small[128] / (float)E + g_small[129] / (float)E;
}

// ---------------- host launch ----------------
extern "C" void kernel_launch(void* const* d_in, const int* in_sizes, int n_in,
                              void* d_out, int out_size) {
    const float* nf   = (const float*)d_in[0];
    const float* ef   = (const float*)d_in[1];
    const int*   src  = (const int*)d_in[2];
    const int*   dst  = (const int*)d_in[3];
    const int*   perm = (const int*)d_in[4];
    const float* Wa1  = (const float*)d_in[5];
    const float* ba1  = (const float*)d_in[6];
    const float* We1  = (const float*)d_in[7];
    const float* be1  = (const float*)d_in[8];
    const float* Wa2  = (const float*)d_in[9];
    const float* ba2  = (const float*)d_in[10];
    const float* We2  = (const float*)d_in[11];
    const float* be2  = (const float*)d_in[12];
    const float* Wbil = (const float*)d_in[13];
    const float* bbil = (const float*)d_in[14];

    int N = in_sizes[0] / 64;
    int E = in_sizes[2];
    if (N > NMAX) N = NMAX;
    if (E > EMAX) E = EMAX;

    static int attr_done = 0;
    if (!attr_done) {
        cudaFuncSetAttribute(layer_kernel<true>,  cudaFuncAttributeMaxDynamicSharedMemorySize, SM_BYTES);
        cudaFuncSetAttribute(layer_kernel<false>, cudaFuncAttributeMaxDynamicSharedMemorySize, SM_BYTES);
        attr_done = 1;
    }

    float *p_aggh1, *p_agge1, *p_agg2, *p_h1, *p_ac1, *p_ac2, *p_V1, *p_V2, *p_small;
    int* p_degi;
    cudaGetSymbolAddress((void**)&p_degi, g_degi);
    cudaGetSymbolAddress((void**)&p_aggh1, g_aggh1);
    cudaGetSymbolAddress((void**)&p_agge1, g_agge1);
    cudaGetSymbolAddress((void**)&p_agg2, g_agg2);
    cudaGetSymbolAddress((void**)&p_h1, g_h1);
    cudaGetSymbolAddress((void**)&p_ac1, g_ac1);
    cudaGetSymbolAddress((void**)&p_ac2, g_ac2);
    cudaGetSymbolAddress((void**)&p_V1, g_V1);
    cudaGetSymbolAddress((void**)&p_V2, g_V2);
    cudaGetSymbolAddress((void**)&p_small, g_small);

    const int B = 256;
    auto g = [](long long n) { return (unsigned)((n + 255) / 256); };
    int layer_grid = (N + 127) / 128;
    unsigned g16 = g((long long)N * 16), g32 = g((long long)N * 32);

    // Setup
    zero_kernel<<<g(N), B>>>((float*)p_degi, N);
    count_kernel<<<g(E), B>>>(dst, E);
    scan_kernel<<<1, 1024>>>(N, E);
    fill_kernel<<<g(E), B>>>(src, dst, E);
    gather1_pos_kernel<<<g32, B>>>(nf, ef, N);
    vprep_kernel<<<g(128 * 64), B>>>(We1, p_V1);
    vprep_kernel<<<g(128 * 64), B>>>(We2, p_V2);
    zero_kernel<<<1, 192>>>(p_small, 192);

    // ======== POS ========
    layer_kernel<true><<<layer_grid, 256, SM_BYTES>>>(nf, p_aggh1, p_agge1, Wa1, ba1, p_V1, p_h1, p_ac1, N);
    gather2_kernel<<<g32, B>>>(be1, N);
    layer_kernel<false><<<layer_grid, 256, SM_BYTES>>>(p_h1, p_agg2, p_agg2 + (long long)NMAX * 64, Wa2, ba2, p_V2, nullptr, p_ac2, N);
    colsum_csr_kernel<<<1024, 256>>>(be2, N);
    summary_kernel<<<1, 64>>>(Wbil, E);
    score_csr_kernel<true><<<2048, 256>>>(be2, bbil, N, 0);

    // ======== NEG ========
    gather_ef_neg_kernel<<<g16, B>>>(ef, perm, N);
    layer_kernel<true><<<layer_grid, 256, SM_BYTES>>>(nf, p_aggh1, p_agge1, Wa1, ba1, p_V1, p_h1, p_ac1, N);
    gather2_kernel<<<g32, B>>>(be1, N);
    layer_kernel<false><<<layer_grid, 256, SM_BYTES>>>(p_h1, p_agg2, p_agg2 + (long long)NMAX * 64, Wa2, ba2, p_V2, nullptr, p_ac2, N);
    score_csr_kernel<false><<<2048, 256>>>(be2, bbil, N, 1);

    final_kernel<<<1, 1>>>((float*)d_out, E);
}